// round 2
// baseline (speedup 1.0000x reference)
#include <cuda_runtime.h>

// RNN_26938034880941: vanilla tanh RNN  B=4096, S=512, I=1, H=16, O=1
// Round 2: 2 independent batch recurrences per thread (ILP x2).
// 16 threads per batch (one hidden unit j per thread), 4 batches per warp,
// 16 batches per 128-thread block, grid = 256 blocks.
// h exchanged via ping-pong shared rows (160B stride), one __syncwarp per step.
// Dot product: packed fma.rn.f32x2, 4 accumulators + tree add.
// tanh via ex2/rcp (abs err ~1e-6, safe through 512-step recurrence).

#define TWO_LOG2E 2.88539008177792681472f  // 2*log2(e)

__device__ __forceinline__ unsigned long long pack2(float a, float b) {
    unsigned long long r;
    asm("mov.b64 %0, {%1, %2};" : "=l"(r) : "f"(a), "f"(b));
    return r;
}
__device__ __forceinline__ unsigned long long fma2(unsigned long long a,
                                                   unsigned long long b,
                                                   unsigned long long c) {
    unsigned long long d;
    asm("fma.rn.f32x2 %0, %1, %2, %3;" : "=l"(d) : "l"(a), "l"(b), "l"(c));
    return d;
}
__device__ __forceinline__ unsigned long long mul2(unsigned long long a,
                                                   unsigned long long b) {
    unsigned long long d;
    asm("mul.rn.f32x2 %0, %1, %2;" : "=l"(d) : "l"(a), "l"(b));
    return d;
}
__device__ __forceinline__ unsigned long long add2(unsigned long long a,
                                                   unsigned long long b) {
    unsigned long long d;
    asm("add.rn.f32x2 %0, %1, %2;" : "=l"(d) : "l"(a), "l"(b));
    return d;
}
__device__ __forceinline__ float hsum2(unsigned long long a) {
    float lo, hi;
    asm("mov.b64 {%0, %1}, %2;" : "=f"(lo), "=f"(hi) : "l"(a));
    return lo + hi;
}
// tanh(z) = 1 - 2/(exp(2z)+1). ex2/rcp approx: abs error ~1e-6, robust at +-inf.
__device__ __forceinline__ float tanh_fast(float z) {
    float q = z * TWO_LOG2E;
    float e;
    asm("ex2.approx.f32 %0, %1;" : "=f"(e) : "f"(q));
    float d = e + 1.0f;
    float r;
    asm("rcp.approx.f32 %0, %1;" : "=f"(r) : "f"(d));
    return fmaf(-2.0f, r, 1.0f);
}

__global__ void __launch_bounds__(128)
rnn_kernel(const float* __restrict__ x,     // [4096,512,1]
           const float* __restrict__ Wih,   // [16,1]
           const float* __restrict__ Whh,   // [16,16]
           const float* __restrict__ bih,   // [16]
           const float* __restrict__ bhh,   // [16]
           const float* __restrict__ Wfc,   // [1,16]
           const float* __restrict__ bfc,   // [1]
           float* __restrict__ out)         // [4096,1]
{
    // 16 batches per block. Per batch: 40-float row (ping 0-15, pong 16-31, pad)
    // 160B stride keeps the two thread-groups' STS on different banks and keeps
    // 16B alignment for vector LDS.
    __shared__ __align__(16) float hbuf[16][40];
    __shared__ __align__(16) float xbuf[16][2][64];

    const int tid  = threadIdx.x;
    const int lane = tid & 31;
    const int warp = tid >> 5;
    const int g    = lane >> 4;   // group within warp (0/1)
    const int j    = lane & 15;   // hidden unit owned by this thread
    const int bibA = warp * 4 + g;        // first batch-in-block (0..15)
    const int bibB = bibA + 2;            // second batch-in-block
    const int batchA = blockIdx.x * 16 + bibA;
    const int batchB = blockIdx.x * 16 + bibB;
    const float* xrowA = x + (size_t)batchA * 512;
    const float* xrowB = x + (size_t)batchB * 512;

    // ---- weights into registers (row j of W_hh, packed into f32x2 pairs) ----
    unsigned long long Wp[8];
#pragma unroll
    for (int i = 0; i < 8; ++i)
        Wp[i] = pack2(Whh[j * 16 + 2 * i], Whh[j * 16 + 2 * i + 1]);
    const float wihj = Wih[j];
    const float bbj  = bih[j] + bhh[j];

    // ---- x chunk 0 -> smem, chunk 1 -> registers (prefetch), both batches ----
    *(float4*)&xbuf[bibA][0][j * 4] = *(const float4*)(xrowA + j * 4);
    *(float4*)&xbuf[bibB][0][j * 4] = *(const float4*)(xrowB + j * 4);
    float4 preA = *(const float4*)(xrowA + 64 + j * 4);
    float4 preB = *(const float4*)(xrowB + 64 + j * 4);

    // ---- h0 = 0 (both ping and pong) ----
    hbuf[bibA][j]      = 0.0f;
    hbuf[bibA][16 + j] = 0.0f;
    hbuf[bibB][j]      = 0.0f;
    hbuf[bibB][16 + j] = 0.0f;
    __syncwarp();

    float hA = 0.0f, hB = 0.0f;

    // One recurrence step for BOTH batches: read h from ping PIN, write POUT.
#define RNN_STEP2(PIN, POUT, XIDX)                                          \
    do {                                                                    \
        __syncwarp();                                                       \
        float xbiasA = fmaf(xcA[(XIDX)], wihj, bbj);                        \
        float xbiasB = fmaf(xcB[(XIDX)], wihj, bbj);                        \
        const ulonglong2* hpA = (const ulonglong2*)&hbuf[bibA][(PIN) * 16]; \
        const ulonglong2* hpB = (const ulonglong2*)&hbuf[bibB][(PIN) * 16]; \
        ulonglong2 A01 = hpA[0], A23 = hpA[1];                              \
        ulonglong2 B01 = hpB[0], B23 = hpB[1];                              \
        ulonglong2 A45 = hpA[2], A67 = hpA[3];                              \
        ulonglong2 B45 = hpB[2], B67 = hpB[3];                              \
        unsigned long long a0 = mul2(A01.x, Wp[0]);                         \
        unsigned long long a1 = mul2(A01.y, Wp[1]);                         \
        unsigned long long a2 = mul2(A23.x, Wp[2]);                         \
        unsigned long long a3 = mul2(A23.y, Wp[3]);                         \
        unsigned long long b0 = mul2(B01.x, Wp[0]);                         \
        unsigned long long b1 = mul2(B01.y, Wp[1]);                         \
        unsigned long long b2 = mul2(B23.x, Wp[2]);                         \
        unsigned long long b3 = mul2(B23.y, Wp[3]);                         \
        a0 = fma2(A45.x, Wp[4], a0);                                        \
        a1 = fma2(A45.y, Wp[5], a1);                                        \
        a2 = fma2(A67.x, Wp[6], a2);                                        \
        a3 = fma2(A67.y, Wp[7], a3);                                        \
        b0 = fma2(B45.x, Wp[4], b0);                                        \
        b1 = fma2(B45.y, Wp[5], b1);                                        \
        b2 = fma2(B67.x, Wp[6], b2);                                        \
        b3 = fma2(B67.y, Wp[7], b3);                                        \
        a0 = add2(a0, a1);                                                  \
        a2 = add2(a2, a3);                                                  \
        b0 = add2(b0, b1);                                                  \
        b2 = add2(b2, b3);                                                  \
        a0 = add2(a0, a2);                                                  \
        b0 = add2(b0, b2);                                                  \
        float zA = xbiasA + hsum2(a0);                                      \
        float zB = xbiasB + hsum2(b0);                                      \
        hA = tanh_fast(zA);                                                 \
        hB = tanh_fast(zB);                                                 \
        hbuf[bibA][(POUT) * 16 + j] = hA;                                   \
        hbuf[bibB][(POUT) * 16 + j] = hB;                                   \
    } while (0)

#pragma unroll 1
    for (int c = 0; c < 8; ++c) {  // 8 chunks x 64 steps = 512
        const float* xcA = xbuf[bibA][c & 1];
        const float* xcB = xbuf[bibB][c & 1];

        // first half: steps 0..31 of this chunk
#pragma unroll 4
        for (int t2 = 0; t2 < 32; t2 += 2) {
            RNN_STEP2(0, 1, t2);
            RNN_STEP2(1, 0, t2 + 1);
        }

        // mid-chunk: commit prefetched chunk c+1 to smem, start LDG for c+2.
        // (consumed only after future __syncwarp's; same-group ordering is safe)
        *(float4*)&xbuf[bibA][(c + 1) & 1][j * 4] = preA;
        *(float4*)&xbuf[bibB][(c + 1) & 1][j * 4] = preB;
        if (c < 6) {
            preA = *(const float4*)(xrowA + (c + 2) * 64 + j * 4);
            preB = *(const float4*)(xrowB + (c + 2) * 64 + j * 4);
        }

        // second half: steps 32..63
#pragma unroll 4
        for (int t2 = 32; t2 < 64; t2 += 2) {
            RNN_STEP2(0, 1, t2);
            RNN_STEP2(1, 0, t2 + 1);
        }
    }
#undef RNN_STEP2

    // ---- epilogue: out[b] = sum_j h_j * Wfc[j] + bfc (reduce within 16-lane group) ----
    const float wfcj = Wfc[j];
    float vA = hA * wfcj;
    float vB = hB * wfcj;
#pragma unroll
    for (int m = 8; m >= 1; m >>= 1) {
        vA += __shfl_xor_sync(0xffffffffu, vA, m);
        vB += __shfl_xor_sync(0xffffffffu, vB, m);
    }
    if (j == 0) {
        const float bias = bfc[0];
        out[batchA] = vA + bias;
        out[batchB] = vB + bias;
    }
}

extern "C" void kernel_launch(void* const* d_in, const int* in_sizes, int n_in,
                              void* d_out, int out_size) {
    const float* x   = (const float*)d_in[0];
    const float* Wih = (const float*)d_in[1];
    const float* Whh = (const float*)d_in[2];
    const float* bih = (const float*)d_in[3];
    const float* bhh = (const float*)d_in[4];
    const float* Wfc = (const float*)d_in[5];
    const float* bfc = (const float*)d_in[6];
    float* out = (float*)d_out;

    // 4096 batches / 16 per block = 256 blocks, 128 threads each
    rnn_kernel<<<256, 128>>>(x, Wih, Whh, bih, bhh, Wfc, bfc, out);
}

// round 3
// speedup vs baseline: 1.2970x; 1.2970x over previous
#include <cuda_runtime.h>

// RNN_26938034880941: vanilla tanh RNN  B=4096, S=512, I=1, H=16, O=1
// Round 3: R1 mapping (16 lanes/batch, 2 batches/warp, 512 blocks x 128) with:
//  - NO per-step __syncwarp (converged warp; in-warp LSU program order; asm
//    volatile memory clobbers on the h-row STS/LDS stop compiler reordering)
//  - recurrence carried as r = 1/(exp(2z)+1); h = 1-2r folded into weights:
//      q = sum_k (-2c*Whh)[j,k] * r_k + c*(rowsum_j + b_ih + b_hh) + c*wih_j*x
//    loop nonlinearity is just ex2 -> +1 -> rcp  (c = 2*log2(e))
//  - x-bias folded into accumulator init, computed in prior step's shadow
//  - batch h-rows 64B apart -> the warp's two groups use disjoint bank halves

#define TWO_LOG2E 2.88539008177792681472f  // 2*log2(e)

__device__ __forceinline__ unsigned long long pack2(float a, float b) {
    unsigned long long r;
    asm("mov.b64 %0, {%1, %2};" : "=l"(r) : "f"(a), "f"(b));
    return r;
}
__device__ __forceinline__ unsigned long long fma2(unsigned long long a,
                                                   unsigned long long b,
                                                   unsigned long long c) {
    unsigned long long d;
    asm("fma.rn.f32x2 %0, %1, %2, %3;" : "=l"(d) : "l"(a), "l"(b), "l"(c));
    return d;
}
__device__ __forceinline__ unsigned long long mul2(unsigned long long a,
                                                   unsigned long long b) {
    unsigned long long d;
    asm("mul.rn.f32x2 %0, %1, %2;" : "=l"(d) : "l"(a), "l"(b));
    return d;
}
__device__ __forceinline__ unsigned long long add2(unsigned long long a,
                                                   unsigned long long b) {
    unsigned long long d;
    asm("add.rn.f32x2 %0, %1, %2;" : "=l"(d) : "l"(a), "l"(b));
    return d;
}
__device__ __forceinline__ float hsum2(unsigned long long a) {
    float lo, hi;
    asm("mov.b64 {%0, %1}, %2;" : "=f"(lo), "=f"(hi) : "l"(a));
    return lo + hi;
}
// Ordered smem ops for the h-row exchange (no syncwarp: converged-warp
// program order + memory clobber give STS->LDS RAW ordering within the warp).
__device__ __forceinline__ void lds_v2u64(unsigned long long& a,
                                          unsigned long long& b, unsigned sa) {
    asm volatile("ld.shared.v2.b64 {%0, %1}, [%2];"
                 : "=l"(a), "=l"(b) : "r"(sa) : "memory");
}
__device__ __forceinline__ void sts_f32(unsigned sa, float v) {
    asm volatile("st.shared.f32 [%0], %1;" :: "r"(sa), "f"(v) : "memory");
}

__global__ void __launch_bounds__(128)
rnn_kernel(const float* __restrict__ x,     // [4096,512,1]
           const float* __restrict__ Wih,   // [16,1]
           const float* __restrict__ Whh,   // [16,16]
           const float* __restrict__ bih,   // [16]
           const float* __restrict__ bhh,   // [16]
           const float* __restrict__ Wfc,   // [1,16]
           const float* __restrict__ bfc,   // [1]
           float* __restrict__ out)         // [4096,1]
{
    // 8 batches per block; r-rows 64B apart (16 floats) -> warp's two groups
    // hit disjoint bank halves (banks 0-15 vs 16-31). 16B aligned for v2.b64.
    __shared__ __align__(16) float rbuf[8][16];
    __shared__ __align__(16) float xbuf[8][2][64];

    const int tid  = threadIdx.x;
    const int lane = tid & 31;
    const int warp = tid >> 5;
    const int g    = lane >> 4;   // group within warp (0/1)
    const int j    = lane & 15;   // hidden unit owned by this thread
    const int bib  = warp * 2 + g;            // batch within block (0..7)
    const int batch = blockIdx.x * 8 + bib;   // global batch
    const float* xrow = x + (size_t)batch * 512;

    // ---- weights: row j of W_hh, scaled by -2c, packed f32x2; rowsum for bias fold ----
    const float4 w0 = *(const float4*)(Whh + j * 16 + 0);
    const float4 w1 = *(const float4*)(Whh + j * 16 + 4);
    const float4 w2 = *(const float4*)(Whh + j * 16 + 8);
    const float4 w3 = *(const float4*)(Whh + j * 16 + 12);
    const float rowsum = (w0.x + w0.y + w0.z + w0.w) + (w1.x + w1.y + w1.z + w1.w)
                       + (w2.x + w2.y + w2.z + w2.w) + (w3.x + w3.y + w3.z + w3.w);
    const float m = -2.0f * TWO_LOG2E;
    unsigned long long Wp[8];
    Wp[0] = pack2(m * w0.x, m * w0.y);  Wp[1] = pack2(m * w0.z, m * w0.w);
    Wp[2] = pack2(m * w1.x, m * w1.y);  Wp[3] = pack2(m * w1.z, m * w1.w);
    Wp[4] = pack2(m * w2.x, m * w2.y);  Wp[5] = pack2(m * w2.z, m * w2.w);
    Wp[6] = pack2(m * w3.x, m * w3.y);  Wp[7] = pack2(m * w3.z, m * w3.w);
    const float cw = TWO_LOG2E * Wih[j];
    const float B2 = TWO_LOG2E * (rowsum + bih[j] + bhh[j]);

    // shared addresses (32-bit) for this lane's row / store slot
    const unsigned hrow_sa = (unsigned)__cvta_generic_to_shared(&rbuf[bib][0]);
    const unsigned hst_sa  = hrow_sa + (unsigned)(j * 4);

    // ---- x chunk 0 -> smem, chunk 1 -> registers (prefetch) ----
    *(float4*)&xbuf[bib][0][j * 4] = *(const float4*)(xrow + j * 4);
    float4 pre = *(const float4*)(xrow + 64 + j * 4);

    // ---- r0 = 0.5 (h0 = 0) ----
    rbuf[bib][j] = 0.5f;
    __syncwarp();   // one-time: order init stores before first asm LDS

    float rcur = 0.5f;

    // One recurrence step. q = dot(-2c*W, r) + (c*wih*x + B2); r = rcp(ex2(q)+1).
#define RNN_STEP(XIDX)                                                  \
    do {                                                                \
        float xv = xc[(XIDX)];                                          \
        unsigned long long qxp = pack2(fmaf(xv, cw, B2), 0.0f);         \
        unsigned long long h0, h1, h2, h3, h4, h5, h6, h7;              \
        lds_v2u64(h0, h1, hrow_sa + 0);                                 \
        lds_v2u64(h2, h3, hrow_sa + 16);                                \
        lds_v2u64(h4, h5, hrow_sa + 32);                                \
        lds_v2u64(h6, h7, hrow_sa + 48);                                \
        unsigned long long a0 = mul2(h0, Wp[0]);                        \
        unsigned long long a1 = fma2(h1, Wp[1], qxp);                   \
        a0 = fma2(h2, Wp[2], a0);                                       \
        a1 = fma2(h3, Wp[3], a1);                                       \
        a0 = fma2(h4, Wp[4], a0);                                       \
        a1 = fma2(h5, Wp[5], a1);                                       \
        a0 = fma2(h6, Wp[6], a0);                                       \
        a1 = fma2(h7, Wp[7], a1);                                       \
        a0 = add2(a0, a1);                                              \
        float q = hsum2(a0);                                            \
        float e;                                                        \
        asm("ex2.approx.f32 %0, %1;" : "=f"(e) : "f"(q));               \
        float dd = e + 1.0f;                                            \
        asm("rcp.approx.f32 %0, %1;" : "=f"(rcur) : "f"(dd));           \
        sts_f32(hst_sa, rcur);                                          \
    } while (0)

#pragma unroll 1
    for (int c = 0; c < 8; ++c) {  // 8 chunks x 64 steps = 512
        const float* xc = xbuf[bib][c & 1];

#pragma unroll 8
        for (int t = 0; t < 32; ++t)
            RNN_STEP(t);

        // mid-chunk: commit prefetched chunk c+1, start LDG for c+2.
        // (other buffer; consumed only next chunk; in-warp order suffices)
        *(float4*)&xbuf[bib][(c + 1) & 1][j * 4] = pre;
        if (c < 6)
            pre = *(const float4*)(xrow + (c + 2) * 64 + j * 4);

#pragma unroll 8
        for (int t = 32; t < 64; ++t)
            RNN_STEP(t);
    }
#undef RNN_STEP

    // ---- epilogue: h = 1-2r; out[b] = sum_j h_j*Wfc[j] + bfc ----
    const float hj = fmaf(-2.0f, rcur, 1.0f);
    float v = hj * Wfc[j];
#pragma unroll
    for (int msk = 8; msk >= 1; msk >>= 1)
        v += __shfl_xor_sync(0xffffffffu, v, msk);
    if (j == 0)
        out[batch] = v + bfc[0];
}

extern "C" void kernel_launch(void* const* d_in, const int* in_sizes, int n_in,
                              void* d_out, int out_size) {
    const float* x   = (const float*)d_in[0];
    const float* Wih = (const float*)d_in[1];
    const float* Whh = (const float*)d_in[2];
    const float* bih = (const float*)d_in[3];
    const float* bhh = (const float*)d_in[4];
    const float* Wfc = (const float*)d_in[5];
    const float* bfc = (const float*)d_in[6];
    float* out = (float*)d_out;

    rnn_kernel<<<512, 128>>>(x, Wih, Whh, bih, bhh, Wfc, bfc, out);
}

// round 4
// speedup vs baseline: 1.5462x; 1.1921x over previous
#include <cuda_runtime.h>

// RNN_26938034880941: vanilla tanh RNN  B=4096, S=512, I=1, H=16, O=1
// Round 4: R3 skeleton (16 lanes/batch, 2 batches/warp, 512x128, no per-step
// sync) with:
//  - MUFU.TANH (tanh.approx.f32) for steps 0..447; exact ex2/rcp tanh for the
//    last 64 steps. Contraction (rho ~0.86 observed) decays early approx error
//    by ~5e-5 before the output: predicted extra error ~2e-7.
//  - buffer carries h directly (plain weights); exact steps pay one extra
//    FMUL (z -> 2*log2e*z) + trailing FMA (h = 1-2r).
//  - x fetched by LDG.128 quad w/ depth-2 register prefetch: NO x smem, no
//    chunk machinery. In-loop smem ops: 4 LDS + 1 STS only.

#define TWO_LOG2E 2.88539008177792681472f  // 2*log2(e)

__device__ __forceinline__ unsigned long long pack2(float a, float b) {
    unsigned long long r;
    asm("mov.b64 %0, {%1, %2};" : "=l"(r) : "f"(a), "f"(b));
    return r;
}
__device__ __forceinline__ unsigned long long fma2(unsigned long long a,
                                                   unsigned long long b,
                                                   unsigned long long c) {
    unsigned long long d;
    asm("fma.rn.f32x2 %0, %1, %2, %3;" : "=l"(d) : "l"(a), "l"(b), "l"(c));
    return d;
}
__device__ __forceinline__ unsigned long long mul2(unsigned long long a,
                                                   unsigned long long b) {
    unsigned long long d;
    asm("mul.rn.f32x2 %0, %1, %2;" : "=l"(d) : "l"(a), "l"(b));
    return d;
}
__device__ __forceinline__ unsigned long long add2(unsigned long long a,
                                                   unsigned long long b) {
    unsigned long long d;
    asm("add.rn.f32x2 %0, %1, %2;" : "=l"(d) : "l"(a), "l"(b));
    return d;
}
// Ordered smem ops for the h-row exchange (converged warp; in-warp LSU program
// order gives STS->LDS RAW; memory clobber stops compiler reordering).
__device__ __forceinline__ void lds_v2u64(unsigned long long& a,
                                          unsigned long long& b, unsigned sa) {
    asm volatile("ld.shared.v2.b64 {%0, %1}, [%2];"
                 : "=l"(a), "=l"(b) : "r"(sa) : "memory");
}
__device__ __forceinline__ void sts_f32(unsigned sa, float v) {
    asm volatile("st.shared.f32 [%0], %1;" :: "r"(sa), "f"(v) : "memory");
}

__global__ void __launch_bounds__(128)
rnn_kernel(const float* __restrict__ x,     // [4096,512,1]
           const float* __restrict__ Wih,   // [16,1]
           const float* __restrict__ Whh,   // [16,16]
           const float* __restrict__ bih,   // [16]
           const float* __restrict__ bhh,   // [16]
           const float* __restrict__ Wfc,   // [1,16]
           const float* __restrict__ bfc,   // [1]
           float* __restrict__ out)         // [4096,1]
{
    // 8 batches per block; h-rows 64B apart -> the warp's two groups use
    // disjoint bank halves. Only smem in the kernel.
    __shared__ __align__(16) float hbuf[8][16];

    const int tid  = threadIdx.x;
    const int lane = tid & 31;
    const int warp = tid >> 5;
    const int g    = lane >> 4;   // group within warp (0/1)
    const int j    = lane & 15;   // hidden unit owned by this thread
    const int bib  = warp * 2 + g;            // batch within block (0..7)
    const int batch = blockIdx.x * 8 + bib;   // global batch
    const float* xrow = x + (size_t)batch * 512;

    // ---- plain weights: row j of W_hh packed into f32x2 pairs ----
    const float4 w0 = *(const float4*)(Whh + j * 16 + 0);
    const float4 w1 = *(const float4*)(Whh + j * 16 + 4);
    const float4 w2 = *(const float4*)(Whh + j * 16 + 8);
    const float4 w3 = *(const float4*)(Whh + j * 16 + 12);
    unsigned long long Wp[8];
    Wp[0] = pack2(w0.x, w0.y);  Wp[1] = pack2(w0.z, w0.w);
    Wp[2] = pack2(w1.x, w1.y);  Wp[3] = pack2(w1.z, w1.w);
    Wp[4] = pack2(w2.x, w2.y);  Wp[5] = pack2(w2.z, w2.w);
    Wp[6] = pack2(w3.x, w3.y);  Wp[7] = pack2(w3.z, w3.w);
    const float wihj = Wih[j];
    const float bj   = bih[j] + bhh[j];

    const unsigned hrow_sa = (unsigned)__cvta_generic_to_shared(&hbuf[bib][0]);
    const unsigned hst_sa  = hrow_sa + (unsigned)(j * 4);

    // ---- h0 = 0 ----
    hbuf[bib][j] = 0.0f;
    __syncwarp();   // one-time: order init stores before first asm LDS

    float hcur = 0.0f;

    // ---- x quad prefetch pipeline (4 steps per float4, depth 2) ----
    float4 cur = *(const float4*)(xrow + 0);
    float4 nxt = *(const float4*)(xrow + 4);

    // Shared dot front-end: z = qx + sum_k W[j,k] * h_k
#define DOT_Z(QX, ZOUT)                                                 \
        unsigned long long h0, h1, h2, h3, h4, h5, h6, h7;              \
        lds_v2u64(h0, h1, hrow_sa + 0);                                 \
        lds_v2u64(h2, h3, hrow_sa + 16);                                \
        lds_v2u64(h4, h5, hrow_sa + 32);                                \
        lds_v2u64(h6, h7, hrow_sa + 48);                                \
        unsigned long long a0 = mul2(h0, Wp[0]);                        \
        unsigned long long a1 = mul2(h1, Wp[1]);                        \
        a0 = fma2(h2, Wp[2], a0);                                       \
        a1 = fma2(h3, Wp[3], a1);                                       \
        a0 = fma2(h4, Wp[4], a0);                                       \
        a1 = fma2(h5, Wp[5], a1);                                       \
        a0 = fma2(h6, Wp[6], a0);                                       \
        a1 = fma2(h7, Wp[7], a1);                                       \
        a0 = add2(a0, a1);                                              \
        float zlo, zhi;                                                 \
        asm("mov.b64 {%0, %1}, %2;" : "=f"(zlo), "=f"(zhi) : "l"(a0));  \
        float ZOUT = ((QX) + zlo) + zhi;

    // Fast step: h = tanh.approx(z)
#define STEP_FAST(QX)                                                   \
    do {                                                                \
        DOT_Z(QX, z)                                                    \
        asm("tanh.approx.f32 %0, %1;" : "=f"(hcur) : "f"(z));           \
        sts_f32(hst_sa, hcur);                                          \
    } while (0)

    // Exact step: h = 1 - 2/(ex2(2*log2e*z)+1)
#define STEP_EXACT(QX)                                                  \
    do {                                                                \
        DOT_Z(QX, z)                                                    \
        float q = z * TWO_LOG2E;                                        \
        float e;                                                        \
        asm("ex2.approx.f32 %0, %1;" : "=f"(e) : "f"(q));               \
        float dd = e + 1.0f;                                            \
        float r;                                                        \
        asm("rcp.approx.f32 %0, %1;" : "=f"(r) : "f"(dd));              \
        hcur = fmaf(-2.0f, r, 1.0f);                                    \
        sts_f32(hst_sa, hcur);                                          \
    } while (0)

    // ---- phase 1: steps 0..447 fast (112 quads) ----
#pragma unroll 2
    for (int t4 = 0; t4 < 112; ++t4) {
        const int nidx = t4 + 2;  // always < 128 here (max 113)
        float4 tmp = *(const float4*)(xrow + nidx * 4);
        float qx0 = fmaf(cur.x, wihj, bj);
        float qx1 = fmaf(cur.y, wihj, bj);
        float qx2 = fmaf(cur.z, wihj, bj);
        float qx3 = fmaf(cur.w, wihj, bj);
        STEP_FAST(qx0);
        STEP_FAST(qx1);
        STEP_FAST(qx2);
        STEP_FAST(qx3);
        cur = nxt;
        nxt = tmp;
    }

    // ---- phase 2: steps 448..511 exact (16 quads) ----
#pragma unroll 2
    for (int t4 = 112; t4 < 128; ++t4) {
        const int nidx = (t4 + 2 < 128) ? (t4 + 2) : 127;
        float4 tmp = *(const float4*)(xrow + nidx * 4);
        float qx0 = fmaf(cur.x, wihj, bj);
        float qx1 = fmaf(cur.y, wihj, bj);
        float qx2 = fmaf(cur.z, wihj, bj);
        float qx3 = fmaf(cur.w, wihj, bj);
        STEP_EXACT(qx0);
        STEP_EXACT(qx1);
        STEP_EXACT(qx2);
        STEP_EXACT(qx3);
        cur = nxt;
        nxt = tmp;
    }
#undef STEP_FAST
#undef STEP_EXACT
#undef DOT_Z

    // ---- epilogue: out[b] = sum_j h_j * Wfc[j] + bfc ----
    float v = hcur * Wfc[j];
#pragma unroll
    for (int msk = 8; msk >= 1; msk >>= 1)
        v += __shfl_xor_sync(0xffffffffu, v, msk);
    if (j == 0)
        out[batch] = v + bfc[0];
}

extern "C" void kernel_launch(void* const* d_in, const int* in_sizes, int n_in,
                              void* d_out, int out_size) {
    const float* x   = (const float*)d_in[0];
    const float* Wih = (const float*)d_in[1];
    const float* Whh = (const float*)d_in[2];
    const float* bih = (const float*)d_in[3];
    const float* bhh = (const float*)d_in[4];
    const float* Wfc = (const float*)d_in[5];
    const float* bfc = (const float*)d_in[6];
    float* out = (float*)d_out;

    rnn_kernel<<<512, 128>>>(x, Wih, Whh, bih, bhh, Wfc, bfc, out);
}